// round 12
// baseline (speedup 1.0000x reference)
#include <cuda_runtime.h>

#define N_FFT  4096
#define M_FFT  2048
#define F_LEN  2049
#define B_SZ   32
#define C_SZ   8
#define E_NUM  8
#define NROW   (B_SZ * C_SZ)     // 256
#define NTF    256               // threads for FFT kernels (1 radix-8 group each)
#define OTILE  128
#define OBLK   17                // ceil(2049/128)
#define OSPAN  (OBLK * OTILE)    // 2176
#define KSPL   65                // k chunks of 32 (65*32 = 2080 >= 2049)

// ---------------- device scratch (no allocations allowed) ----------------
__device__ float2 g_freq[NROW * F_LEN];
__device__ float  g_gate[B_SZ * F_LEN];
__device__ float  g_mean[NROW];
__device__ float  g_std[NROW];
__device__ float  g_scores[B_SZ * E_NUM];
__device__ int    g_idx[E_NUM + 1];
__device__ float  g_part[KSPL][B_SZ][OSPAN];
__device__ float2 g_tw[1024];               // e^{-2*pi*i*k/4096}, k in [0,1024)
__device__ float  g_dummy[16 + B_SZ * E_NUM];

#define RT2H 0.70710678118654752440f

// ---------------- helpers ----------------
__device__ __forceinline__ int brev11(int i) { return (int)(__brev((unsigned)i) >> 21); }

__device__ __forceinline__ float2 cmul(float2 a, float2 b) {
    return make_float2(a.x * b.x - a.y * b.y, a.x * b.y + a.y * b.x);
}

__device__ __forceinline__ void bf(float2& u, float2& v, float2 w) {
    float2 t = cmul(w, v);
    v = make_float2(u.x - t.x, u.y - t.y);
    u = make_float2(u.x + t.x, u.y + t.y);
}
__device__ __forceinline__ void bf1(float2& u, float2& v) {   // w = 1
    float2 t = v;
    v = make_float2(u.x - t.x, u.y - t.y);
    u = make_float2(u.x + t.x, u.y + t.y);
}

// e^{-2*pi*i*k/4096}, k in [0,2048) — from global table (L1-resident, 8KB)
__device__ __forceinline__ float2 w4096g(int k) {
    if (k < 1024) return g_tw[k];
    float2 u = g_tw[k - 1024];                // * exp(-i*pi/2) = -i
    return make_float2(u.y, -u.x);
}

// ---------------- radix-8 DIT pass covering stages S, S+1, S+2 ----------------
// 256 threads, one 8-point group each. In-place on smem a[2048]. Twiddles from gmem.
template <int S, bool INV>
__device__ __forceinline__ void radix8_pass(float2* a, int u) {
    const int h = 1 << S;
    int j  = u & (h - 1);
    int i0 = ((u >> S) << (S + 3)) + j;

    float2 p0 = a[i0];
    float2 p1 = a[i0 + h];
    float2 p2 = a[i0 + 2 * h];
    float2 p3 = a[i0 + 3 * h];
    float2 p4 = a[i0 + 4 * h];
    float2 p5 = a[i0 + 5 * h];
    float2 p6 = a[i0 + 6 * h];
    float2 p7 = a[i0 + 7 * h];

    float2 wa = w4096g(j << (11 - S));
    float2 wb = g_tw[j << (10 - S)];
    float2 wc = g_tw[j << (9 - S)];
    if (INV) { wa.y = -wa.y; wb.y = -wb.y; wc.y = -wc.y; }

    // stage S (radix-2, twiddle wa)
    bf(p0, p1, wa); bf(p2, p3, wa); bf(p4, p5, wa); bf(p6, p7, wa);
    // stage S+1: wb for even pairs, (∓i)*wb for odd pairs
    float2 wb1 = INV ? make_float2(-wb.y, wb.x) : make_float2(wb.y, -wb.x);
    bf(p0, p2, wb); bf(p1, p3, wb1); bf(p4, p6, wb); bf(p5, p7, wb1);
    // stage S+2: wc * {1, C1, ∓i, C3}
    const float2 C1 = INV ? make_float2(RT2H,  RT2H) : make_float2(RT2H, -RT2H);
    const float2 C3 = INV ? make_float2(-RT2H, RT2H) : make_float2(-RT2H, -RT2H);
    float2 wc1 = cmul(wc, C1);
    float2 wc2 = INV ? make_float2(-wc.y, wc.x) : make_float2(wc.y, -wc.x);
    float2 wc3 = cmul(wc, C3);
    bf(p0, p4, wc); bf(p1, p5, wc1); bf(p2, p6, wc2); bf(p3, p7, wc3);

    a[i0]         = p0;
    a[i0 + h]     = p1;
    a[i0 + 2 * h] = p2;
    a[i0 + 3 * h] = p3;
    a[i0 + 4 * h] = p4;
    a[i0 + 5 * h] = p5;
    a[i0 + 6 * h] = p6;
    a[i0 + 7 * h] = p7;
}

// final radix-4 (stages 9,10) in-place to smem (used by k1)
template <bool INV>
__device__ __forceinline__ void radix4_final_smem(float2* a, int tid) {
    #pragma unroll
    for (int j = tid; j < 512; j += NTF) {
        float2 p0 = a[j], p1 = a[j + 512], p2 = a[j + 1024], p3 = a[j + 1536];
        float2 w1 = w4096g(j << 2);
        float2 w2 = w4096g(j << 1);
        if (INV) { w1.y = -w1.y; w2.y = -w2.y; }
        bf(p0, p1, w1); bf(p2, p3, w1);
        float2 w2b = INV ? make_float2(-w2.y, w2.x) : make_float2(w2.y, -w2.x);
        bf(p0, p2, w2); bf(p1, p3, w2b);
        a[j] = p0; a[j + 512] = p1; a[j + 1024] = p2; a[j + 1536] = p3;
    }
}

// ---------------- kernel 0: twiddle table + boundaries ----------------
__global__ void k0_init(const float* __restrict__ raw, float* __restrict__ out_bounds) {
    int k = blockIdx.x * blockDim.x + threadIdx.x;
    if (k < 1024) {
        float s, c;
        sincospif(-(float)k / 2048.0f, &s, &c);
        g_tw[k] = make_float2(c, s);
    }
    if (k == 0) {
        float b[E_NUM - 1];
        for (int i = 0; i < E_NUM - 1; i++) b[i] = 1.0f / (1.0f + expf(-raw[i]));
        for (int i = 1; i < E_NUM - 1; i++) {
            float v = b[i]; int j = i - 1;
            while (j >= 0 && b[j] > v) { b[j + 1] = b[j]; j--; }
            b[j + 1] = v;
        }
        float bd[E_NUM + 1];
        bd[0] = 0.f;
        for (int i = 0; i < E_NUM - 1; i++) bd[i + 1] = b[i];
        bd[E_NUM] = 1.f;
        for (int i = 0; i <= E_NUM; i++) {
            out_bounds[i] = bd[i];
            g_idx[i] = (int)floorf(bd[i] * (float)F_LEN);
        }
        g_idx[E_NUM] = F_LEN;
    }
}

// ---------------- kernel 1: norm + forward rfft via half-length trick ----------------
__global__ __launch_bounds__(NTF, 4) void k1_norm_fft(const float* __restrict__ x) {
    __shared__ float2 a[M_FFT];        // 16 KB
    __shared__ float  red[16];

    int row = blockIdx.x;
    int tid = threadIdx.x;
    int lane = tid & 31, wid = tid >> 5;

    const float4* xr = (const float4*)(x + (size_t)row * N_FFT);
    float s = 0.f, ss = 0.f;
    for (int i = tid; i < N_FFT / 4; i += NTF) {
        float4 v = xr[i];
        a[2 * i]     = make_float2(v.x, v.y);
        a[2 * i + 1] = make_float2(v.z, v.w);
        s  += (v.x + v.y) + (v.z + v.w);
        ss += v.x * v.x + v.y * v.y + v.z * v.z + v.w * v.w;
    }
    #pragma unroll
    for (int o = 16; o; o >>= 1) {
        s  += __shfl_xor_sync(0xffffffffu, s, o);
        ss += __shfl_xor_sync(0xffffffffu, ss, o);
    }
    if (lane == 0) { red[wid] = s; red[wid + 8] = ss; }
    __syncthreads();
    float sum = 0.f, sumsq = 0.f;
    #pragma unroll
    for (int i = 0; i < 8; i++) { sum += red[i]; sumsq += red[8 + i]; }

    float mean = sum * (1.0f / N_FFT);
    float var  = (sumsq - sum * mean) * (1.0f / (N_FFT - 1)) + 1e-5f;
    float stdv = sqrtf(var);
    float inv  = 1.0f / stdv;
    if (tid == 0) { g_mean[row] = mean; g_std[row] = stdv; }
    __syncthreads();

    // normalize + bit-reversal permutation (disjoint swap pairs)
    for (int n = tid; n < M_FFT; n += NTF) {
        int r = brev11(n);
        if (r > n) {
            float2 u = a[n], v = a[r];
            a[n] = make_float2((v.x - mean) * inv, (v.y - mean) * inv);
            a[r] = make_float2((u.x - mean) * inv, (u.y - mean) * inv);
        } else if (r == n) {
            float2 u = a[n];
            a[n] = make_float2((u.x - mean) * inv, (u.y - mean) * inv);
        }
    }
    __syncthreads();

    radix8_pass<0, false>(a, tid); __syncthreads();
    radix8_pass<3, false>(a, tid); __syncthreads();
    radix8_pass<6, false>(a, tid); __syncthreads();
    radix4_final_smem<false>(a, tid); __syncthreads();

    // unpack real-FFT halves
    float2* fr = g_freq + (size_t)row * F_LEN;
    for (int k = tid; k < M_FFT; k += NTF) {
        float2 Zk = a[k];
        float2 Zm = a[(M_FFT - k) & (M_FFT - 1)];
        float2 P = make_float2(Zk.x + Zm.x, Zk.y - Zm.y);
        float2 Q = make_float2(Zk.x - Zm.x, Zk.y + Zm.y);
        float2 w = w4096g(k);
        float2 t = cmul(w, Q);
        fr[k] = make_float2(0.5f * (P.x + t.y), 0.5f * (P.y - t.x));
    }
    if (tid == 0) fr[M_FFT] = make_float2(a[0].x - a[0].y, 0.f);
}

// ---------------- kernel 1b: gating input = mean_c |freq| ----------------
__global__ void k1b_gate() {
    int i = blockIdx.x * blockDim.x + threadIdx.x;
    if (i >= B_SZ * F_LEN) return;
    int b = i / F_LEN;
    int f = i - b * F_LEN;
    float acc = 0.f;
    #pragma unroll
    for (int c = 0; c < C_SZ; c++) {
        float2 v = g_freq[(size_t)(b * C_SZ + c) * F_LEN + f];
        acc += sqrtf(v.x * v.x + v.y * v.y);
    }
    g_gate[i] = acc * (1.0f / C_SZ);
}

// ---------------- kernel 2b: partial GEMM, single-buffer, k-chunk 32 ----------------
__global__ __launch_bounds__(256, 4) void k2b_part(const float* __restrict__ W1) {
    __shared__ float Gs[32][33];       // 4.2 KB
    __shared__ float Ws[OTILE][33];    // 16.9 KB

    int t  = threadIdx.x;
    int tx = t & 31;            // o lanes: o = oBase + tx + 32*j
    int ty = t >> 5;            // b groups: b = 4*ty + i
    int oBase = blockIdx.x * OTILE;
    int k0 = blockIdx.y * 32;

    #pragma unroll
    for (int i = 0; i < 4; i++) {
        int idx = t + i * 256, bb = idx >> 5, kk = idx & 31;
        Gs[bb][kk] = (k0 + kk < F_LEN) ? g_gate[bb * F_LEN + k0 + kk] : 0.f;
    }
    #pragma unroll
    for (int i = 0; i < 16; i++) {
        int idx = t + i * 256, oo = idx >> 5, kk = idx & 31;
        int o = oBase + oo;
        Ws[oo][kk] = (o < F_LEN && k0 + kk < F_LEN) ? W1[(size_t)o * F_LEN + k0 + kk] : 0.f;
    }
    __syncthreads();

    float acc[4][4] = {};
    #pragma unroll
    for (int kk = 0; kk < 32; kk++) {
        float g0 = Gs[4 * ty + 0][kk];
        float g1 = Gs[4 * ty + 1][kk];
        float g2 = Gs[4 * ty + 2][kk];
        float g3 = Gs[4 * ty + 3][kk];
        float w0 = Ws[tx][kk];
        float w1 = Ws[tx + 32][kk];
        float w2 = Ws[tx + 64][kk];
        float w3 = Ws[tx + 96][kk];
        acc[0][0] = fmaf(g0, w0, acc[0][0]); acc[0][1] = fmaf(g0, w1, acc[0][1]);
        acc[0][2] = fmaf(g0, w2, acc[0][2]); acc[0][3] = fmaf(g0, w3, acc[0][3]);
        acc[1][0] = fmaf(g1, w0, acc[1][0]); acc[1][1] = fmaf(g1, w1, acc[1][1]);
        acc[1][2] = fmaf(g1, w2, acc[1][2]); acc[1][3] = fmaf(g1, w3, acc[1][3]);
        acc[2][0] = fmaf(g2, w0, acc[2][0]); acc[2][1] = fmaf(g2, w1, acc[2][1]);
        acc[2][2] = fmaf(g2, w2, acc[2][2]); acc[2][3] = fmaf(g2, w3, acc[2][3]);
        acc[3][0] = fmaf(g3, w0, acc[3][0]); acc[3][1] = fmaf(g3, w1, acc[3][1]);
        acc[3][2] = fmaf(g3, w2, acc[3][2]); acc[3][3] = fmaf(g3, w3, acc[3][3]);
    }

    #pragma unroll
    for (int i = 0; i < 4; i++)
        #pragma unroll
        for (int j = 0; j < 4; j++)
            g_part[blockIdx.y][4 * ty + i][oBase + tx + 32 * j] = acc[i][j];
}

// ---------------- kernel 2c: partial-sum + bias + relu + logits + softmax ----------------
__global__ __launch_bounds__(256) void k2c_gate(const float* __restrict__ W2,
                                                const float* __restrict__ b1,
                                                const float* __restrict__ b2,
                                                float* __restrict__ out_scores) {
    __shared__ float red[256];
    __shared__ float logits[E_NUM];
    int b = blockIdx.x, tid = threadIdx.x;
    float acc[E_NUM];
    #pragma unroll
    for (int e = 0; e < E_NUM; e++) acc[e] = 0.f;
    for (int f = tid; f < F_LEN; f += 256) {
        float s = b1[f];
        #pragma unroll 5
        for (int ks = 0; ks < KSPL; ks++) s += g_part[ks][b][f];
        float hv = fmaxf(s, 0.f);
        #pragma unroll
        for (int e = 0; e < E_NUM; e++) acc[e] = fmaf(hv, W2[e * F_LEN + f], acc[e]);
    }
    for (int e = 0; e < E_NUM; e++) {
        red[tid] = acc[e]; __syncthreads();
        for (int o = 128; o > 0; o >>= 1) { if (tid < o) red[tid] += red[tid + o]; __syncthreads(); }
        if (tid == 0) logits[e] = red[0] + b2[e];
        __syncthreads();
    }
    if (tid == 0) {
        float mx = logits[0];
        for (int e = 1; e < E_NUM; e++) mx = fmaxf(mx, logits[e]);
        float sm = 0.f, ex[E_NUM];
        for (int e = 0; e < E_NUM; e++) { ex[e] = expf(logits[e] - mx); sm += ex[e]; }
        float is = 1.0f / sm;
        for (int e = 0; e < E_NUM; e++) {
            float v = ex[e] * is;
            g_scores[b * E_NUM + e] = v;
            out_scores[b * E_NUM + e] = v;
        }
    }
}

// spectrum prep for inverse half-length FFT
__device__ __forceinline__ float2 prep_band(const float2* __restrict__ fr,
                                            int k, int lo, int hi) {
    int km = M_FFT - k;
    float2 A = make_float2(0.f, 0.f), B = make_float2(0.f, 0.f);
    if (k >= lo && k < hi)   A = fr[k];
    if (km >= lo && km < hi) B = fr[km];
    float2 P  = make_float2(A.x + B.x, A.y - B.y);
    float2 Qw = make_float2(A.x - B.x, A.y + B.y);
    float2 w = w4096g(k);
    float2 cw = make_float2(w.x, -w.y);
    float2 Xo2 = cmul(Qw, cw);
    return make_float2(P.x - Xo2.y, P.y + Xo2.x);
}

// fused gather + first radix-8 (j=0, constant twiddles) for inverse kernels.
#define GATHER_RADIX8_INV(PREP)                                                   \
    {                                                                             \
        int base = (int)(__brev((unsigned)tid) >> 24);                            \
        float2 p0 = PREP(base);                                                   \
        float2 p1 = PREP(base + 1024);                                            \
        float2 p2 = PREP(base + 512);                                             \
        float2 p3 = PREP(base + 1536);                                            \
        float2 p4 = PREP(base + 256);                                             \
        float2 p5 = PREP(base + 1280);                                            \
        float2 p6 = PREP(base + 768);                                             \
        float2 p7 = PREP(base + 1792);                                            \
        bf1(p0, p1); bf1(p2, p3); bf1(p4, p5); bf1(p6, p7);                       \
        bf1(p0, p2);                                                              \
        { float2 t3 = make_float2(-p3.y, p3.x);                                   \
          float2 u = p1; p1 = make_float2(u.x + t3.x, u.y + t3.y);                \
          p3 = make_float2(u.x - t3.x, u.y - t3.y); }                             \
        bf1(p4, p6);                                                              \
        { float2 t7 = make_float2(-p7.y, p7.x);                                   \
          float2 u = p5; p5 = make_float2(u.x + t7.x, u.y + t7.y);                \
          p7 = make_float2(u.x - t7.x, u.y - t7.y); }                             \
        bf1(p0, p4);                                                              \
        bf(p1, p5, make_float2(RT2H, RT2H));                                      \
        { float2 t6 = make_float2(-p6.y, p6.x);                                   \
          float2 u = p2; p2 = make_float2(u.x + t6.x, u.y + t6.y);                \
          p6 = make_float2(u.x - t6.x, u.y - t6.y); }                             \
        bf(p3, p7, make_float2(-RT2H, RT2H));                                     \
        int o8 = tid * 8;                                                         \
        a[o8] = p0; a[o8 + 1] = p1; a[o8 + 2] = p2; a[o8 + 3] = p3;               \
        a[o8 + 4] = p4; a[o8 + 5] = p5; a[o8 + 6] = p6; a[o8 + 7] = p7;           \
    }

// ---------------- kernel 3: expert band irfft (radix-8, fully fused) ----------------
// out_exp has an ODD float offset -> scalar stores only.
__global__ __launch_bounds__(NTF, 4) void k3_expert(float* __restrict__ out_exp) {
    __shared__ float2 a[M_FFT];        // 16 KB only

    int blk = blockIdx.x;                 // b*64 + e*8 + c
    int c = blk & 7;
    int e = (blk >> 3) & 7;
    int b = blk >> 6;
    int row = b * C_SZ + c;
    int tid = threadIdx.x;

    int lo = g_idx[e], hi = g_idx[e + 1];

    const float2* fr = g_freq + (size_t)row * F_LEN;

    #define PREP3(kk) prep_band(fr, (kk), lo, hi)
    GATHER_RADIX8_INV(PREP3)
    #undef PREP3
    __syncthreads();

    radix8_pass<3, true>(a, tid); __syncthreads();
    radix8_pass<6, true>(a, tid); __syncthreads();

    // final radix-4 fused with scaled scalar store
    float* o = out_exp + (size_t)blk * N_FFT;
    const float sc = 1.0f / (float)N_FFT;
    #pragma unroll
    for (int j = tid; j < 512; j += NTF) {
        float2 p0 = a[j], p1 = a[j + 512], p2 = a[j + 1024], p3 = a[j + 1536];
        float2 w1 = w4096g(j << 2);  w1.y = -w1.y;
        float2 w2 = w4096g(j << 1);  w2.y = -w2.y;
        bf(p0, p1, w1); bf(p2, p3, w1);
        float2 w2b = make_float2(-w2.y, w2.x);
        bf(p0, p2, w2); bf(p1, p3, w2b);
        o[2 * j]            = p0.x * sc;  o[2 * j + 1]            = p0.y * sc;
        o[2 * (j + 512)]    = p1.x * sc;  o[2 * (j + 512) + 1]    = p1.y * sc;
        o[2 * (j + 1024)]   = p2.x * sc;  o[2 * (j + 1024) + 1]   = p2.y * sc;
        o[2 * (j + 1536)]   = p3.x * sc;  o[2 * (j + 1536) + 1]   = p3.y * sc;
    }
}

// ---------------- kernel 4: gated combine irfft + denorm (radix-8 fused) ----------------
__device__ __forceinline__ float2 prep_gated(const float2* __restrict__ fr,
                                             int k, const int* s_idx, const float* s_g) {
    int km = M_FFT - k;
    int ea = 0, eb = 0;
    while (ea < E_NUM - 1 && k  >= s_idx[ea + 1]) ea++;
    while (eb < E_NUM - 1 && km >= s_idx[eb + 1]) eb++;
    float ga = s_g[ea], gb = s_g[eb];
    float2 Af = fr[k];
    float2 Bf = fr[km];
    float2 A = make_float2(Af.x * ga, Af.y * ga);
    float2 B = make_float2(Bf.x * gb, Bf.y * gb);
    float2 P  = make_float2(A.x + B.x, A.y - B.y);
    float2 Qw = make_float2(A.x - B.x, A.y + B.y);
    float2 w = w4096g(k);
    float2 cw = make_float2(w.x, -w.y);
    float2 Xo2 = cmul(Qw, cw);
    return make_float2(P.x - Xo2.y, P.y + Xo2.x);
}

__global__ __launch_bounds__(NTF, 4) void k4_combined(float* __restrict__ out_comb) {
    __shared__ float2 a[M_FFT];
    __shared__ int   s_idx[E_NUM + 1];
    __shared__ float s_g[E_NUM];

    int row = blockIdx.x;
    int b = row / C_SZ;
    int tid = threadIdx.x;

    if (tid < E_NUM + 1) s_idx[tid] = g_idx[tid];
    if (tid >= 32 && tid < 32 + E_NUM) s_g[tid - 32] = g_scores[b * E_NUM + (tid - 32)];
    __syncthreads();

    const float2* fr = g_freq + (size_t)row * F_LEN;

    #define PREP4(kk) prep_gated(fr, (kk), s_idx, s_g)
    GATHER_RADIX8_INV(PREP4)
    #undef PREP4
    __syncthreads();

    radix8_pass<3, true>(a, tid); __syncthreads();
    radix8_pass<6, true>(a, tid); __syncthreads();

    float mean = g_mean[row], stdv = g_std[row];
    float2* o = (float2*)(out_comb + (size_t)row * N_FFT);   // 8B-aligned
    const float sc = 1.0f / (float)N_FFT;
    #pragma unroll
    for (int j = tid; j < 512; j += NTF) {
        float2 p0 = a[j], p1 = a[j + 512], p2 = a[j + 1024], p3 = a[j + 1536];
        float2 w1 = w4096g(j << 2);  w1.y = -w1.y;
        float2 w2 = w4096g(j << 1);  w2.y = -w2.y;
        bf(p0, p1, w1); bf(p2, p3, w1);
        float2 w2b = make_float2(-w2.y, w2.x);
        bf(p0, p2, w2); bf(p1, p3, w2b);
        o[j]        = make_float2(fmaf(p0.x * sc, stdv, mean), fmaf(p0.y * sc, stdv, mean));
        o[j + 512]  = make_float2(fmaf(p1.x * sc, stdv, mean), fmaf(p1.y * sc, stdv, mean));
        o[j + 1024] = make_float2(fmaf(p2.x * sc, stdv, mean), fmaf(p2.y * sc, stdv, mean));
        o[j + 1536] = make_float2(fmaf(p3.x * sc, stdv, mean), fmaf(p3.y * sc, stdv, mean));
    }
}

// ---------------- launch ----------------
extern "C" void kernel_launch(void* const* d_in, const int* in_sizes, int n_in,
                              void* d_out, int out_size) {
    const float* x   = (const float*)d_in[0];
    const float* raw = (const float*)d_in[1];
    const float* W1  = (const float*)d_in[2];
    const float* b1  = (const float*)d_in[3];
    const float* W2  = (const float*)d_in[4];
    const float* b2  = (const float*)d_in[5];
    float* out = (float*)d_out;

    const int comb_n   = B_SZ * C_SZ * N_FFT;
    const int bounds_n = E_NUM + 1;
    const int scores_n = B_SZ * E_NUM;
    const int exp_n    = B_SZ * E_NUM * C_SZ * N_FFT;
    const int total_n  = comb_n + bounds_n + scores_n + exp_n;

    bool full = (out_size >= total_n);

    float* out_comb = out;
    float* out_bounds;
    float* out_scores;
    float* out_exp = nullptr;

    if (full) {
        out_bounds = out + comb_n;
        out_scores = out_bounds + bounds_n;
        out_exp    = out_scores + scores_n;
    } else {
        cudaGetSymbolAddress((void**)&out_bounds, g_dummy);
        out_scores = out_bounds + 16;
    }

    k0_init<<<4, 256>>>(raw, out_bounds);
    k1_norm_fft<<<NROW, NTF>>>(x);
    k1b_gate<<<(B_SZ * F_LEN + 255) / 256, 256>>>();
    k2b_part<<<dim3(OBLK, KSPL), 256>>>(W1);
    k2c_gate<<<B_SZ, 256>>>(W2, b1, b2, out_scores);
    if (full) {
        k3_expert<<<B_SZ * E_NUM * C_SZ, NTF>>>(out_exp);
    }
    k4_combined<<<NROW, NTF>>>(out_comb);
}

// round 15
// speedup vs baseline: 1.2651x; 1.2651x over previous
#include <cuda_runtime.h>

#define N_FFT  4096
#define M_FFT  2048
#define F_LEN  2049
#define B_SZ   32
#define C_SZ   8
#define E_NUM  8
#define NROW   (B_SZ * C_SZ)     // 256
#define NTF    256               // threads for FFT kernels (1 radix-8 group each)
#define OTILE  128
#define OBLK   17                // ceil(2049/128)
#define OSPAN  (OBLK * OTILE)    // 2176
#define KSPL   65                // k chunks of 32 (65*32 = 2080 >= 2049)

// ---------------- device scratch (no allocations allowed) ----------------
__device__ float2 g_freq[NROW * F_LEN];
__device__ float  g_gate[B_SZ * F_LEN];
__device__ float  g_mean[NROW];
__device__ float  g_std[NROW];
__device__ float  g_h[B_SZ * F_LEN];
__device__ float  g_scores[B_SZ * E_NUM];
__device__ int    g_idx[E_NUM + 1];
__device__ float  g_part[KSPL][B_SZ][OSPAN];
__device__ float2 g_tw[1024];               // e^{-2*pi*i*k/4096}, k in [0,1024)
__device__ float  g_dummy[16 + B_SZ * E_NUM];

#define RT2H 0.70710678118654752440f

// ---------------- helpers ----------------
__device__ __forceinline__ int brev11(int i) { return (int)(__brev((unsigned)i) >> 21); }

__device__ __forceinline__ float2 cmul(float2 a, float2 b) {
    return make_float2(a.x * b.x - a.y * b.y, a.x * b.y + a.y * b.x);
}

__device__ __forceinline__ void bf(float2& u, float2& v, float2 w) {
    float2 t = cmul(w, v);
    v = make_float2(u.x - t.x, u.y - t.y);
    u = make_float2(u.x + t.x, u.y + t.y);
}
__device__ __forceinline__ void bf1(float2& u, float2& v) {   // w = 1
    float2 t = v;
    v = make_float2(u.x - t.x, u.y - t.y);
    u = make_float2(u.x + t.x, u.y + t.y);
}

__device__ __forceinline__ void load_tw(float2* tw, int tid) {
    #pragma unroll
    for (int k = tid; k < 1024; k += NTF) tw[k] = g_tw[k];
}

// e^{-2*pi*i*k/4096}, k in [0,2048) — smem table
__device__ __forceinline__ float2 w4096(const float2* tw, int k) {
    if (k < 1024) return tw[k];
    float2 u = tw[k - 1024];
    return make_float2(u.y, -u.x);
}
// same from global (used only in the fused gathers, L1/L2-resident)
__device__ __forceinline__ float2 w4096g(int k) {
    if (k < 1024) return g_tw[k];
    float2 u = g_tw[k - 1024];
    return make_float2(u.y, -u.x);
}

// ---------------- radix-8 DIT pass covering stages S, S+1, S+2 ----------------
// 256 threads, one 8-point group each. In-place on smem a[2048].
template <int S, bool INV>
__device__ __forceinline__ void radix8_pass(float2* a, const float2* tw, int u) {
    const int h = 1 << S;
    int j  = u & (h - 1);
    int i0 = ((u >> S) << (S + 3)) + j;

    float2 p0 = a[i0];
    float2 p1 = a[i0 + h];
    float2 p2 = a[i0 + 2 * h];
    float2 p3 = a[i0 + 3 * h];
    float2 p4 = a[i0 + 4 * h];
    float2 p5 = a[i0 + 5 * h];
    float2 p6 = a[i0 + 6 * h];
    float2 p7 = a[i0 + 7 * h];

    float2 wa = w4096(tw, j << (11 - S));
    float2 wb = tw[j << (10 - S)];
    float2 wc = tw[j << (9 - S)];
    if (INV) { wa.y = -wa.y; wb.y = -wb.y; wc.y = -wc.y; }

    // stage S (radix-2, twiddle wa)
    bf(p0, p1, wa); bf(p2, p3, wa); bf(p4, p5, wa); bf(p6, p7, wa);
    // stage S+1: wb for even pairs, (∓i)*wb for odd pairs
    float2 wb1 = INV ? make_float2(-wb.y, wb.x) : make_float2(wb.y, -wb.x);
    bf(p0, p2, wb); bf(p1, p3, wb1); bf(p4, p6, wb); bf(p5, p7, wb1);
    // stage S+2: wc * {1, C1, ∓i, C3}
    const float2 C1 = INV ? make_float2(RT2H,  RT2H) : make_float2(RT2H, -RT2H);
    const float2 C3 = INV ? make_float2(-RT2H, RT2H) : make_float2(-RT2H, -RT2H);
    float2 wc1 = cmul(wc, C1);
    float2 wc2 = INV ? make_float2(-wc.y, wc.x) : make_float2(wc.y, -wc.x);
    float2 wc3 = cmul(wc, C3);
    bf(p0, p4, wc); bf(p1, p5, wc1); bf(p2, p6, wc2); bf(p3, p7, wc3);

    a[i0]         = p0;
    a[i0 + h]     = p1;
    a[i0 + 2 * h] = p2;
    a[i0 + 3 * h] = p3;
    a[i0 + 4 * h] = p4;
    a[i0 + 5 * h] = p5;
    a[i0 + 6 * h] = p6;
    a[i0 + 7 * h] = p7;
}

// final radix-4 (stages 9,10) in-place to smem (used by k1)
template <bool INV>
__device__ __forceinline__ void radix4_final_smem(float2* a, const float2* tw, int tid) {
    #pragma unroll
    for (int j = tid; j < 512; j += NTF) {
        float2 p0 = a[j], p1 = a[j + 512], p2 = a[j + 1024], p3 = a[j + 1536];
        float2 w1 = w4096(tw, j << 2);
        float2 w2 = w4096(tw, j << 1);
        if (INV) { w1.y = -w1.y; w2.y = -w2.y; }
        bf(p0, p1, w1); bf(p2, p3, w1);
        float2 w2b = INV ? make_float2(-w2.y, w2.x) : make_float2(w2.y, -w2.x);
        bf(p0, p2, w2); bf(p1, p3, w2b);
        a[j] = p0; a[j + 512] = p1; a[j + 1024] = p2; a[j + 1536] = p3;
    }
}

// ---------------- kernel 0: twiddle table + boundaries ----------------
__global__ void k0_init(const float* __restrict__ raw, float* __restrict__ out_bounds) {
    int k = blockIdx.x * blockDim.x + threadIdx.x;
    if (k < 1024) {
        float s, c;
        sincospif(-(float)k / 2048.0f, &s, &c);
        g_tw[k] = make_float2(c, s);
    }
    if (k == 0) {
        float b[E_NUM - 1];
        for (int i = 0; i < E_NUM - 1; i++) b[i] = 1.0f / (1.0f + expf(-raw[i]));
        for (int i = 1; i < E_NUM - 1; i++) {
            float v = b[i]; int j = i - 1;
            while (j >= 0 && b[j] > v) { b[j + 1] = b[j]; j--; }
            b[j + 1] = v;
        }
        float bd[E_NUM + 1];
        bd[0] = 0.f;
        for (int i = 0; i < E_NUM - 1; i++) bd[i + 1] = b[i];
        bd[E_NUM] = 1.f;
        for (int i = 0; i <= E_NUM; i++) {
            out_bounds[i] = bd[i];
            g_idx[i] = (int)floorf(bd[i] * (float)F_LEN);
        }
        g_idx[E_NUM] = F_LEN;
    }
}

// ---------------- kernel 1: norm + forward rfft via half-length trick ----------------
__global__ __launch_bounds__(NTF, 4) void k1_norm_fft(const float* __restrict__ x) {
    __shared__ float2 a[M_FFT];
    __shared__ float2 tw[1024];
    __shared__ float  red[16];

    int row = blockIdx.x;
    int tid = threadIdx.x;
    int lane = tid & 31, wid = tid >> 5;

    load_tw(tw, tid);

    const float4* xr = (const float4*)(x + (size_t)row * N_FFT);
    float s = 0.f, ss = 0.f;
    for (int i = tid; i < N_FFT / 4; i += NTF) {
        float4 v = xr[i];
        a[2 * i]     = make_float2(v.x, v.y);
        a[2 * i + 1] = make_float2(v.z, v.w);
        s  += (v.x + v.y) + (v.z + v.w);
        ss += v.x * v.x + v.y * v.y + v.z * v.z + v.w * v.w;
    }
    #pragma unroll
    for (int o = 16; o; o >>= 1) {
        s  += __shfl_xor_sync(0xffffffffu, s, o);
        ss += __shfl_xor_sync(0xffffffffu, ss, o);
    }
    if (lane == 0) { red[wid] = s; red[wid + 8] = ss; }
    __syncthreads();
    float sum = 0.f, sumsq = 0.f;
    #pragma unroll
    for (int i = 0; i < 8; i++) { sum += red[i]; sumsq += red[8 + i]; }

    float mean = sum * (1.0f / N_FFT);
    float var  = (sumsq - sum * mean) * (1.0f / (N_FFT - 1)) + 1e-5f;
    float stdv = sqrtf(var);
    float inv  = 1.0f / stdv;
    if (tid == 0) { g_mean[row] = mean; g_std[row] = stdv; }
    __syncthreads();

    // normalize + bit-reversal permutation (disjoint swap pairs)
    for (int n = tid; n < M_FFT; n += NTF) {
        int r = brev11(n);
        if (r > n) {
            float2 u = a[n], v = a[r];
            a[n] = make_float2((v.x - mean) * inv, (v.y - mean) * inv);
            a[r] = make_float2((u.x - mean) * inv, (u.y - mean) * inv);
        } else if (r == n) {
            float2 u = a[n];
            a[n] = make_float2((u.x - mean) * inv, (u.y - mean) * inv);
        }
    }
    __syncthreads();

    radix8_pass<0, false>(a, tw, tid); __syncthreads();
    radix8_pass<3, false>(a, tw, tid); __syncthreads();
    radix8_pass<6, false>(a, tw, tid); __syncthreads();
    radix4_final_smem<false>(a, tw, tid); __syncthreads();

    // unpack real-FFT halves
    float2* fr = g_freq + (size_t)row * F_LEN;
    for (int k = tid; k < M_FFT; k += NTF) {
        float2 Zk = a[k];
        float2 Zm = a[(M_FFT - k) & (M_FFT - 1)];
        float2 P = make_float2(Zk.x + Zm.x, Zk.y - Zm.y);
        float2 Q = make_float2(Zk.x - Zm.x, Zk.y + Zm.y);
        float2 w = w4096(tw, k);
        float2 t = cmul(w, Q);
        fr[k] = make_float2(0.5f * (P.x + t.y), 0.5f * (P.y - t.x));
    }
    if (tid == 0) fr[M_FFT] = make_float2(a[0].x - a[0].y, 0.f);
}

// ---------------- kernel 1b: gating input = mean_c |freq| ----------------
__global__ void k1b_gate() {
    int i = blockIdx.x * blockDim.x + threadIdx.x;
    if (i >= B_SZ * F_LEN) return;
    int b = i / F_LEN;
    int f = i - b * F_LEN;
    float acc = 0.f;
    #pragma unroll
    for (int c = 0; c < C_SZ; c++) {
        float2 v = g_freq[(size_t)(b * C_SZ + c) * F_LEN + f];
        acc += sqrtf(v.x * v.x + v.y * v.y);
    }
    g_gate[i] = acc * (1.0f / C_SZ);
}

// ---------------- kernel 2b: partial GEMM, single-buffer, k-chunk 32 ----------------
__global__ __launch_bounds__(256, 4) void k2b_part(const float* __restrict__ W1) {
    __shared__ float Gs[32][33];       // 4.2 KB
    __shared__ float Ws[OTILE][33];    // 16.9 KB

    int t  = threadIdx.x;
    int tx = t & 31;            // o lanes: o = oBase + tx + 32*j
    int ty = t >> 5;            // b groups: b = 4*ty + i
    int oBase = blockIdx.x * OTILE;
    int k0 = blockIdx.y * 32;

    #pragma unroll
    for (int i = 0; i < 4; i++) {
        int idx = t + i * 256, bb = idx >> 5, kk = idx & 31;
        Gs[bb][kk] = (k0 + kk < F_LEN) ? g_gate[bb * F_LEN + k0 + kk] : 0.f;
    }
    #pragma unroll
    for (int i = 0; i < 16; i++) {
        int idx = t + i * 256, oo = idx >> 5, kk = idx & 31;
        int o = oBase + oo;
        Ws[oo][kk] = (o < F_LEN && k0 + kk < F_LEN) ? W1[(size_t)o * F_LEN + k0 + kk] : 0.f;
    }
    __syncthreads();

    float acc[4][4] = {};
    #pragma unroll
    for (int kk = 0; kk < 32; kk++) {
        float g0 = Gs[4 * ty + 0][kk];
        float g1 = Gs[4 * ty + 1][kk];
        float g2 = Gs[4 * ty + 2][kk];
        float g3 = Gs[4 * ty + 3][kk];
        float w0 = Ws[tx][kk];
        float w1 = Ws[tx + 32][kk];
        float w2 = Ws[tx + 64][kk];
        float w3 = Ws[tx + 96][kk];
        acc[0][0] = fmaf(g0, w0, acc[0][0]); acc[0][1] = fmaf(g0, w1, acc[0][1]);
        acc[0][2] = fmaf(g0, w2, acc[0][2]); acc[0][3] = fmaf(g0, w3, acc[0][3]);
        acc[1][0] = fmaf(g1, w0, acc[1][0]); acc[1][1] = fmaf(g1, w1, acc[1][1]);
        acc[1][2] = fmaf(g1, w2, acc[1][2]); acc[1][3] = fmaf(g1, w3, acc[1][3]);
        acc[2][0] = fmaf(g2, w0, acc[2][0]); acc[2][1] = fmaf(g2, w1, acc[2][1]);
        acc[2][2] = fmaf(g2, w2, acc[2][2]); acc[2][3] = fmaf(g2, w3, acc[2][3]);
        acc[3][0] = fmaf(g3, w0, acc[3][0]); acc[3][1] = fmaf(g3, w1, acc[3][1]);
        acc[3][2] = fmaf(g3, w2, acc[3][2]); acc[3][3] = fmaf(g3, w3, acc[3][3]);
    }

    #pragma unroll
    for (int i = 0; i < 4; i++)
        #pragma unroll
        for (int j = 0; j < 4; j++)
            g_part[blockIdx.y][4 * ty + i][oBase + tx + 32 * j] = acc[i][j];
}

// ---------------- kernel 2b-red: sum partials + bias + relu ----------------
__global__ void k2b_red(const float* __restrict__ b1) {
    int i = blockIdx.x * blockDim.x + threadIdx.x;
    if (i >= B_SZ * F_LEN) return;
    int b = i / F_LEN, o = i - b * F_LEN;
    float s = 0.f;
    #pragma unroll 5
    for (int ks = 0; ks < KSPL; ks++) s += g_part[ks][b][o];
    g_h[i] = fmaxf(s + b1[o], 0.f);
}

// ---------------- kernel 2c: logits + softmax ----------------
__global__ __launch_bounds__(256) void k2c_gate(const float* __restrict__ W2,
                                                const float* __restrict__ b2,
                                                float* __restrict__ out_scores) {
    __shared__ float red[256];
    __shared__ float logits[E_NUM];
    int b = blockIdx.x, tid = threadIdx.x;
    float acc[E_NUM];
    #pragma unroll
    for (int e = 0; e < E_NUM; e++) acc[e] = 0.f;
    for (int f = tid; f < F_LEN; f += 256) {
        float hv = g_h[b * F_LEN + f];
        #pragma unroll
        for (int e = 0; e < E_NUM; e++) acc[e] = fmaf(hv, W2[e * F_LEN + f], acc[e]);
    }
    for (int e = 0; e < E_NUM; e++) {
        red[tid] = acc[e]; __syncthreads();
        for (int o = 128; o > 0; o >>= 1) { if (tid < o) red[tid] += red[tid + o]; __syncthreads(); }
        if (tid == 0) logits[e] = red[0] + b2[e];
        __syncthreads();
    }
    if (tid == 0) {
        float mx = logits[0];
        for (int e = 1; e < E_NUM; e++) mx = fmaxf(mx, logits[e]);
        float sm = 0.f, ex[E_NUM];
        for (int e = 0; e < E_NUM; e++) { ex[e] = expf(logits[e] - mx); sm += ex[e]; }
        float is = 1.0f / sm;
        for (int e = 0; e < E_NUM; e++) {
            float v = ex[e] * is;
            g_scores[b * E_NUM + e] = v;
            out_scores[b * E_NUM + e] = v;
        }
    }
}

// spectrum prep for inverse half-length FFT
__device__ __forceinline__ float2 prep_band(const float2* __restrict__ fr,
                                            int k, int lo, int hi) {
    int km = M_FFT - k;
    float2 A = make_float2(0.f, 0.f), B = make_float2(0.f, 0.f);
    if (k >= lo && k < hi)   A = fr[k];
    if (km >= lo && km < hi) B = fr[km];
    float2 P  = make_float2(A.x + B.x, A.y - B.y);
    float2 Qw = make_float2(A.x - B.x, A.y + B.y);
    float2 w = w4096g(k);
    float2 cw = make_float2(w.x, -w.y);
    float2 Xo2 = cmul(Qw, cw);
    return make_float2(P.x - Xo2.y, P.y + Xo2.x);
}

// fused gather + first radix-8 (j=0, constant twiddles) for inverse kernels.
#define GATHER_RADIX8_INV(PREP)                                                   \
    {                                                                             \
        int base = (int)(__brev((unsigned)tid) >> 24);                            \
        float2 p0 = PREP(base);                                                   \
        float2 p1 = PREP(base + 1024);                                            \
        float2 p2 = PREP(base + 512);                                             \
        float2 p3 = PREP(base + 1536);                                            \
        float2 p4 = PREP(base + 256);                                             \
        float2 p5 = PREP(base + 1280);                                            \
        float2 p6 = PREP(base + 768);                                             \
        float2 p7 = PREP(base + 1792);                                            \
        bf1(p0, p1); bf1(p2, p3); bf1(p4, p5); bf1(p6, p7);                       \
        bf1(p0, p2);                                                              \
        { float2 t3 = make_float2(-p3.y, p3.x);                                   \
          float2 u = p1; p1 = make_float2(u.x + t3.x, u.y + t3.y);                \
          p3 = make_float2(u.x - t3.x, u.y - t3.y); }                             \
        bf1(p4, p6);                                                              \
        { float2 t7 = make_float2(-p7.y, p7.x);                                   \
          float2 u = p5; p5 = make_float2(u.x + t7.x, u.y + t7.y);                \
          p7 = make_float2(u.x - t7.x, u.y - t7.y); }                             \
        bf1(p0, p4);                                                              \
        bf(p1, p5, make_float2(RT2H, RT2H));                                      \
        { float2 t6 = make_float2(-p6.y, p6.x);                                   \
          float2 u = p2; p2 = make_float2(u.x + t6.x, u.y + t6.y);                \
          p6 = make_float2(u.x - t6.x, u.y - t6.y); }                             \
        bf(p3, p7, make_float2(-RT2H, RT2H));                                     \
        int o8 = tid * 8;                                                         \
        a[o8] = p0; a[o8 + 1] = p1; a[o8 + 2] = p2; a[o8 + 3] = p3;               \
        a[o8 + 4] = p4; a[o8 + 5] = p5; a[o8 + 6] = p6; a[o8 + 7] = p7;           \
    }

// ---------------- kernel 3: expert band irfft (radix-8, fully fused) ----------------
// out_exp has an ODD float offset -> scalar stores only.
__global__ __launch_bounds__(NTF, 4) void k3_expert(float* __restrict__ out_exp) {
    __shared__ float2 a[M_FFT];
    __shared__ float2 tw[1024];

    int blk = blockIdx.x;                 // b*64 + e*8 + c
    int c = blk & 7;
    int e = (blk >> 3) & 7;
    int b = blk >> 6;
    int row = b * C_SZ + c;
    int tid = threadIdx.x;

    int lo = g_idx[e], hi = g_idx[e + 1];
    load_tw(tw, tid);

    const float2* fr = g_freq + (size_t)row * F_LEN;

    #define PREP3(kk) prep_band(fr, (kk), lo, hi)
    GATHER_RADIX8_INV(PREP3)
    #undef PREP3
    __syncthreads();

    radix8_pass<3, true>(a, tw, tid); __syncthreads();
    radix8_pass<6, true>(a, tw, tid); __syncthreads();

    // final radix-4 fused with scaled scalar store
    float* o = out_exp + (size_t)blk * N_FFT;
    const float sc = 1.0f / (float)N_FFT;
    #pragma unroll
    for (int j = tid; j < 512; j += NTF) {
        float2 p0 = a[j], p1 = a[j + 512], p2 = a[j + 1024], p3 = a[j + 1536];
        float2 w1 = w4096(tw, j << 2);  w1.y = -w1.y;
        float2 w2 = w4096(tw, j << 1);  w2.y = -w2.y;
        bf(p0, p1, w1); bf(p2, p3, w1);
        float2 w2b = make_float2(-w2.y, w2.x);
        bf(p0, p2, w2); bf(p1, p3, w2b);
        o[2 * j]            = p0.x * sc;  o[2 * j + 1]            = p0.y * sc;
        o[2 * (j + 512)]    = p1.x * sc;  o[2 * (j + 512) + 1]    = p1.y * sc;
        o[2 * (j + 1024)]   = p2.x * sc;  o[2 * (j + 1024) + 1]   = p2.y * sc;
        o[2 * (j + 1536)]   = p3.x * sc;  o[2 * (j + 1536) + 1]   = p3.y * sc;
    }
}

// ---------------- kernel 4: gated combine irfft + denorm (radix-8 fused) ----------------
__device__ __forceinline__ float2 prep_gated(const float2* __restrict__ fr,
                                             int k, const int* s_idx, const float* s_g) {
    int km = M_FFT - k;
    int ea = 0, eb = 0;
    while (ea < E_NUM - 1 && k  >= s_idx[ea + 1]) ea++;
    while (eb < E_NUM - 1 && km >= s_idx[eb + 1]) eb++;
    float ga = s_g[ea], gb = s_g[eb];
    float2 Af = fr[k];
    float2 Bf = fr[km];
    float2 A = make_float2(Af.x * ga, Af.y * ga);
    float2 B = make_float2(Bf.x * gb, Bf.y * gb);
    float2 P  = make_float2(A.x + B.x, A.y - B.y);
    float2 Qw = make_float2(A.x - B.x, A.y + B.y);
    float2 w = w4096g(k);
    float2 cw = make_float2(w.x, -w.y);
    float2 Xo2 = cmul(Qw, cw);
    return make_float2(P.x - Xo2.y, P.y + Xo2.x);
}

__global__ __launch_bounds__(NTF, 4) void k4_combined(float* __restrict__ out_comb) {
    __shared__ float2 a[M_FFT];
    __shared__ float2 tw[1024];
    __shared__ int   s_idx[E_NUM + 1];
    __shared__ float s_g[E_NUM];

    int row = blockIdx.x;
    int b = row / C_SZ;
    int tid = threadIdx.x;

    if (tid < E_NUM + 1) s_idx[tid] = g_idx[tid];
    if (tid >= 32 && tid < 32 + E_NUM) s_g[tid - 32] = g_scores[b * E_NUM + (tid - 32)];
    load_tw(tw, tid);
    __syncthreads();

    const float2* fr = g_freq + (size_t)row * F_LEN;

    #define PREP4(kk) prep_gated(fr, (kk), s_idx, s_g)
    GATHER_RADIX8_INV(PREP4)
    #undef PREP4
    __syncthreads();

    radix8_pass<3, true>(a, tw, tid); __syncthreads();
    radix8_pass<6, true>(a, tw, tid); __syncthreads();

    float mean = g_mean[row], stdv = g_std[row];
    float2* o = (float2*)(out_comb + (size_t)row * N_FFT);   // 8B-aligned
    const float sc = 1.0f / (float)N_FFT;
    #pragma unroll
    for (int j = tid; j < 512; j += NTF) {
        float2 p0 = a[j], p1 = a[j + 512], p2 = a[j + 1024], p3 = a[j + 1536];
        float2 w1 = w4096(tw, j << 2);  w1.y = -w1.y;
        float2 w2 = w4096(tw, j << 1);  w2.y = -w2.y;
        bf(p0, p1, w1); bf(p2, p3, w1);
        float2 w2b = make_float2(-w2.y, w2.x);
        bf(p0, p2, w2); bf(p1, p3, w2b);
        o[j]        = make_float2(fmaf(p0.x * sc, stdv, mean), fmaf(p0.y * sc, stdv, mean));
        o[j + 512]  = make_float2(fmaf(p1.x * sc, stdv, mean), fmaf(p1.y * sc, stdv, mean));
        o[j + 1024] = make_float2(fmaf(p2.x * sc, stdv, mean), fmaf(p2.y * sc, stdv, mean));
        o[j + 1536] = make_float2(fmaf(p3.x * sc, stdv, mean), fmaf(p3.y * sc, stdv, mean));
    }
}

// ---------------- launch ----------------
extern "C" void kernel_launch(void* const* d_in, const int* in_sizes, int n_in,
                              void* d_out, int out_size) {
    const float* x   = (const float*)d_in[0];
    const float* raw = (const float*)d_in[1];
    const float* W1  = (const float*)d_in[2];
    const float* b1  = (const float*)d_in[3];
    const float* W2  = (const float*)d_in[4];
    const float* b2  = (const float*)d_in[5];
    float* out = (float*)d_out;

    const int comb_n   = B_SZ * C_SZ * N_FFT;
    const int bounds_n = E_NUM + 1;
    const int scores_n = B_SZ * E_NUM;
    const int exp_n    = B_SZ * E_NUM * C_SZ * N_FFT;
    const int total_n  = comb_n + bounds_n + scores_n + exp_n;

    bool full = (out_size >= total_n);

    float* out_comb = out;
    float* out_bounds;
    float* out_scores;
    float* out_exp = nullptr;

    if (full) {
        out_bounds = out + comb_n;
        out_scores = out_bounds + bounds_n;
        out_exp    = out_scores + scores_n;
    } else {
        cudaGetSymbolAddress((void**)&out_bounds, g_dummy);
        out_scores = out_bounds + 16;
    }

    k0_init<<<4, 256>>>(raw, out_bounds);
    k1_norm_fft<<<NROW, NTF>>>(x);
    k1b_gate<<<(B_SZ * F_LEN + 255) / 256, 256>>>();
    k2b_part<<<dim3(OBLK, KSPL), 256>>>(W1);
    k2b_red<<<(B_SZ * F_LEN + 255) / 256, 256>>>(b1);
    k2c_gate<<<B_SZ, 256>>>(W2, b2, out_scores);
    if (full) {
        k3_expert<<<B_SZ * E_NUM * C_SZ, NTF>>>(out_exp);
    }
    k4_combined<<<NROW, NTF>>>(out_comb);
}